// round 12
// baseline (speedup 1.0000x reference)
#include <cuda_runtime.h>
#include <cuda_bf16.h>

#define C_DIM   10000
#define B_DIM   8192
#define M_SCALE 4.0f
#define THREADS 256
#define N4      (C_DIM / 4)               // 2500 float4 per row
#define FULL_IT (N4 / THREADS)            // 9
#define TAIL_N  (N4 - FULL_IT * THREADS)  // 196

// Per-row loss scratch + completion counter (reset by the last block each run).
__device__ float        g_row_loss[B_DIM];
__device__ unsigned int g_done = 0u;

__global__ __launch_bounds__(THREADS) void ems_fused_kernel(
    const float* __restrict__ inputs,
    const int* __restrict__ targets,   // int32 (JAX default int width)
    float* __restrict__ out)
{
    const int row = blockIdx.x;
    const int tid = threadIdx.x;
    const float4* __restrict__ rowp =
        reinterpret_cast<const float4*>(inputs + (size_t)row * C_DIM);

    // ---- front-batched loads: 9 full + predicated tail (proven fastest) ----
    float4 v[FULL_IT];
    #pragma unroll
    for (int k = 0; k < FULL_IT; k++)
        v[k] = __ldg(&rowp[tid + k * THREADS]);

    const bool has_tail = (tid < TAIL_N);
    float4 vt = has_tail ? __ldg(&rowp[FULL_IT * THREADS + tid])
                         : make_float4(0.f, 0.f, 0.f, 0.f);

    float s = 0.0f;
    #pragma unroll
    for (int k = 0; k < FULL_IT; k++) {
        s += __expf(v[k].x);
        s += __expf(v[k].y);
        s += __expf(v[k].z);
        s += __expf(v[k].w);
    }
    if (has_tail) {
        s += __expf(vt.x);
        s += __expf(vt.y);
        s += __expf(vt.z);
        s += __expf(vt.w);
    }

    // ---- block reduction ----
    #pragma unroll
    for (int off = 16; off > 0; off >>= 1)
        s += __shfl_xor_sync(0xFFFFFFFFu, s, off);

    __shared__ float warp_sums[THREADS / 32];
    __shared__ unsigned int am_last;
    const int lane = tid & 31, wid = tid >> 5;
    if (lane == 0) warp_sums[wid] = s;
    __syncthreads();

    if (wid == 0) {
        float t = (lane < THREADS / 32) ? warp_sums[lane] : 0.0f;
        #pragma unroll
        for (int off = 4; off > 0; off >>= 1)
            t += __shfl_xor_sync(0xFFFFFFFFu, t, off);
        if (lane == 0) {
            const int tgt = targets[row];
            const float xt  = __ldg(inputs + (size_t)row * C_DIM + tgt);
            const float xtm = M_SCALE * xt;
            // replace exp(x_t) by exp(4*x_t) in the row sum
            const float sp = t - __expf(xt) + __expf(xtm);
            g_row_loss[row] = __logf(sp) - xtm;   // plain STG
            __threadfence();                      // release row loss
            // single cheap 32-bit counter atomic per block
            am_last = (atomicAdd(&g_done, 1u) == (unsigned)(B_DIM - 1));
        }
    }
    __syncthreads();

    // ---- last block: final mean over all 8192 row losses (L2-resident) ----
    if (am_last) {
        __threadfence();   // acquire side: make all g_row_loss stores visible
        const float4* __restrict__ p = reinterpret_cast<const float4*>(g_row_loss);
        float4 w[8];       // 2048 float4 total; 8 per thread, front-batched
        #pragma unroll
        for (int k = 0; k < 8; k++)
            w[k] = p[tid + k * THREADS];

        float r = 0.0f;
        #pragma unroll
        for (int k = 0; k < 8; k++)
            r += (w[k].x + w[k].y) + (w[k].z + w[k].w);

        #pragma unroll
        for (int off = 16; off > 0; off >>= 1)
            r += __shfl_xor_sync(0xFFFFFFFFu, r, off);

        if (lane == 0) warp_sums[wid] = r;   // reuse: guarded by syncthreads above
        __syncthreads();

        if (wid == 0) {
            float t = (lane < THREADS / 32) ? warp_sums[lane] : 0.0f;
            #pragma unroll
            for (int off = 4; off > 0; off >>= 1)
                t += __shfl_xor_sync(0xFFFFFFFFu, t, off);
            if (lane == 0) {
                out[0] = t * (1.0f / (float)B_DIM);
                g_done = 0u;   // reset for next graph replay
            }
        }
    }
}

extern "C" void kernel_launch(void* const* d_in, const int* in_sizes, int n_in,
                              void* d_out, int out_size)
{
    const float* inputs = (const float*)d_in[0];
    const int* targets = (const int*)d_in[1];
    float* out = (float*)d_out;

    ems_fused_kernel<<<B_DIM, THREADS>>>(inputs, targets, out);
}

// round 13
// speedup vs baseline: 1.0573x; 1.0573x over previous
#include <cuda_runtime.h>
#include <cuda_bf16.h>

#define C_DIM   10000
#define B_DIM   8192
#define M_SCALE 4.0f
#define THREADS 256
#define N4      (C_DIM / 4)               // 2500 float4 per row
#define FULL_IT (N4 / THREADS)            // 9
#define TAIL_N  (N4 - FULL_IT * THREADS)  // 196

// Per-row loss scratch; overwritten every replay, no reset needed.
__device__ float g_row_loss[B_DIM];

// ---------------- Kernel 1: per-row loss (R9 body + PDL trigger) ------------
__global__ __launch_bounds__(THREADS) void ems_row_kernel(
    const float* __restrict__ inputs,
    const int* __restrict__ targets)   // int32 (JAX default int width)
{
    const int row = blockIdx.x;
    const int tid = threadIdx.x;
    const float4* __restrict__ rowp =
        reinterpret_cast<const float4*>(inputs + (size_t)row * C_DIM);

    // Front-batched loads: 9 full + predicated tail (MLP ~10) — proven fastest.
    float4 v[FULL_IT];
    #pragma unroll
    for (int k = 0; k < FULL_IT; k++)
        v[k] = __ldg(&rowp[tid + k * THREADS]);

    const bool has_tail = (tid < TAIL_N);
    float4 vt = has_tail ? __ldg(&rowp[FULL_IT * THREADS + tid])
                         : make_float4(0.f, 0.f, 0.f, 0.f);

    float s = 0.0f;
    #pragma unroll
    for (int k = 0; k < FULL_IT; k++) {
        s += __expf(v[k].x);
        s += __expf(v[k].y);
        s += __expf(v[k].z);
        s += __expf(v[k].w);
    }
    if (has_tail) {
        s += __expf(vt.x);
        s += __expf(vt.y);
        s += __expf(vt.z);
        s += __expf(vt.w);
    }

    // ---- block reduction ----
    #pragma unroll
    for (int off = 16; off > 0; off >>= 1)
        s += __shfl_xor_sync(0xFFFFFFFFu, s, off);

    __shared__ float warp_sums[THREADS / 32];
    const int lane = tid & 31, wid = tid >> 5;
    if (lane == 0) warp_sums[wid] = s;
    __syncthreads();

    if (wid == 0) {
        float t = (lane < THREADS / 32) ? warp_sums[lane] : 0.0f;
        #pragma unroll
        for (int off = 4; off > 0; off >>= 1)
            t += __shfl_xor_sync(0xFFFFFFFFu, t, off);
        if (lane == 0) {
            const int tgt = targets[row];
            const float xt  = __ldg(inputs + (size_t)row * C_DIM + tgt);
            const float xtm = M_SCALE * xt;
            // replace exp(x_t) by exp(4*x_t) in the row sum
            const float sp = t - __expf(xt) + __expf(xtm);
            g_row_loss[row] = __logf(sp) - xtm;   // plain STG: no fence, no atomics
        }
    }
    __syncthreads();  // order lane0's STG before this CTA's PDL trigger
    // PDL: this CTA is done producing; dependent grid may proceed once all CTAs trigger.
    asm volatile("griddepcontrol.launch_dependents;");
}

// ---------------- Kernel 2: mean of 8192 floats (PDL-gated, 1 block) --------
__global__ __launch_bounds__(THREADS) void ems_reduce_kernel(float* __restrict__ out)
{
    // Wait until the primary grid's pre-trigger stores are visible.
    asm volatile("griddepcontrol.wait;" ::: "memory");

    const int tid = threadIdx.x;
    const float4* __restrict__ p = reinterpret_cast<const float4*>(g_row_loss);
    // 8192 floats = 2048 float4; 8 per thread, all front-batched (L2-resident).
    float4 v[8];
    #pragma unroll
    for (int k = 0; k < 8; k++)
        v[k] = p[tid + k * THREADS];

    float s = 0.0f;
    #pragma unroll
    for (int k = 0; k < 8; k++)
        s += (v[k].x + v[k].y) + (v[k].z + v[k].w);

    #pragma unroll
    for (int off = 16; off > 0; off >>= 1)
        s += __shfl_xor_sync(0xFFFFFFFFu, s, off);

    __shared__ float warp_sums[THREADS / 32];
    const int lane = tid & 31, wid = tid >> 5;
    if (lane == 0) warp_sums[wid] = s;
    __syncthreads();

    if (wid == 0) {
        float t = (lane < THREADS / 32) ? warp_sums[lane] : 0.0f;
        #pragma unroll
        for (int off = 4; off > 0; off >>= 1)
            t += __shfl_xor_sync(0xFFFFFFFFu, t, off);
        if (lane == 0)
            out[0] = t * (1.0f / (float)B_DIM);
    }
}

extern "C" void kernel_launch(void* const* d_in, const int* in_sizes, int n_in,
                              void* d_out, int out_size)
{
    const float* inputs = (const float*)d_in[0];
    const int* targets = (const int*)d_in[1];
    float* out = (float*)d_out;

    ems_row_kernel<<<B_DIM, THREADS>>>(inputs, targets);

    // Secondary launch with Programmatic Stream Serialization: its launch
    // overhead overlaps the primary; griddepcontrol.wait provides ordering.
    cudaLaunchConfig_t cfg = {};
    cfg.gridDim  = dim3(1, 1, 1);
    cfg.blockDim = dim3(THREADS, 1, 1);
    cfg.dynamicSmemBytes = 0;
    cfg.stream = 0;  // same (legacy default) stream the harness captures
    cudaLaunchAttribute attr[1];
    attr[0].id = cudaLaunchAttributeProgrammaticStreamSerialization;
    attr[0].val.programmaticStreamSerializationAllowed = 1;
    cfg.attrs = attr;
    cfg.numAttrs = 1;
    cudaLaunchKernelEx(&cfg, ems_reduce_kernel, out);
}